// round 14
// baseline (speedup 1.0000x reference)
#include <cuda_runtime.h>
#include <cuda_bf16.h>
#include <math.h>

// Problem constants
#define NN   16384
#define EE   8192
#define DIM  256
#define CAP_R 128
#define CAP_C 192
#define LN_EPS 1e-5f

// Weight-plane offsets (elements) inside g_wh / g_wl ([K][N] layout)
#define OFF_WE 0
#define OFF_WN 65536
#define OFF_WR 131072
#define OFF_W1 196608
#define OFF_W2 327680
#define W_TOTAL 458752

// ---------------- static device scratch (no allocations allowed) ------------
__device__ int   g_cols[NN * CAP_R];
__device__ int   g_rows[EE * CAP_C];
__device__ int   g_rcnt[NN];
__device__ int   g_ccnt[EE];
__device__ float g_invsv[NN];
__device__ float g_invse[EE];

__device__ float g_x1a [EE * DIM];
__device__ float g_u   [NN * DIM];
__device__ float g_x0g [NN * DIM];

// bf16 gather sources for the SpMMs (pre-scaled by their row norm factors)
__device__ __nv_bfloat162 g_x0bf [NN * DIM / 2];
__device__ __nv_bfloat162 g_x1abf[EE * DIM / 2];
__device__ __nv_bfloat162 g_x0lbf[NN * DIM / 2];

// bf16 planes for GEMM A operands (hi only; produced by upstream kernels)
__device__ __align__(16) __nv_bfloat16 g_tmpEh[EE * DIM];
__device__ __align__(16) __nv_bfloat16 g_msgh [NN * DIM];
__device__ __align__(16) __nv_bfloat16 g_reth [EE * DIM];
__device__ __align__(16) __nv_bfloat16 g_x0gh [NN * DIM];
__device__ __align__(16) __nv_bfloat16 g_hh   [NN * 2 * DIM];

// pre-split bf16 hi/lo weight planes ([K][N])
__device__ __align__(16) __nv_bfloat16 g_wh[W_TOTAL];
__device__ __align__(16) __nv_bfloat16 g_wl[W_TOTAL];

// ---------------- sparse build + weight prepack (fused; DRAM-bound) ---------
__global__ __launch_bounds__(256) void build_csr_kernel(
    const float* __restrict__ H,
    const float* __restrict__ We, const float* __restrict__ Wn,
    const float* __restrict__ Wr, const float* __restrict__ W1,
    const float* __restrict__ W2)
{
    int gtid = blockIdx.x * blockDim.x + threadIdx.x;
    if (gtid < EE) g_ccnt[gtid] = 0;
    if (gtid < W_TOTAL) {
        const float* src; int off;
        if      (gtid < OFF_WN) { src = We; off = OFF_WE; }
        else if (gtid < OFF_WR) { src = Wn; off = OFF_WN; }
        else if (gtid < OFF_W1) { src = Wr; off = OFF_WR; }
        else if (gtid < OFF_W2) { src = W1; off = OFF_W1; }
        else                    { src = W2; off = OFF_W2; }
        float v = src[gtid - off];
        __nv_bfloat16 h = __float2bfloat16_rn(v);
        g_wh[gtid] = h;
        g_wl[gtid] = __float2bfloat16_rn(v - __bfloat162float(h));
    }

    int warp = gtid >> 5;
    int lane = threadIdx.x & 31;
    if (warp >= NN) return;
    const float* row = H + (size_t)warp * EE;
    int base = 0;
    for (int it = 0; it < EE / 128; it++) {
        float4 v4 = *(const float4*)(row + it * 128 + lane * 4);
        float v[4] = {v4.x, v4.y, v4.z, v4.w};
#pragma unroll
        for (int j = 0; j < 4; j++) {
            unsigned m = __ballot_sync(0xffffffffu, v[j] != 0.0f);
            if (v[j] != 0.0f) {
                int pos = base + __popc(m & ((1u << lane) - 1u));
                if (pos < CAP_R) g_cols[warp * CAP_R + pos] = it * 128 + lane * 4 + j;
            }
            base += __popc(m);
        }
    }
    if (lane == 0) {
        g_rcnt[warp]  = min(base, CAP_R);
        g_invsv[warp] = rsqrtf(fmaxf((float)base, 1.0f));
    }
}

// Fused: CSR->CSC scatter + x0 -> bf16 (pre-scaled by invsv[row]).
__global__ void scatter_cvt_kernel(const float* __restrict__ x0) {
    int tid = blockIdx.x * blockDim.x + threadIdx.x;
    int row = tid >> 7;
    float2 p = *(const float2*)(x0 + (size_t)tid * 2);
    float s = g_invsv[row];
    g_x0bf[tid] = __floats2bfloat162_rn(p.x * s, p.y * s);

    int k = tid & (CAP_R - 1);
    if (k < g_rcnt[row]) {
        int col = g_cols[row * CAP_R + k];
        int p2 = atomicAdd(&g_ccnt[col], 1);
        if (p2 < CAP_C) g_rows[col * CAP_C + p2] = row;
    }
}

// ---------------- SpMM bodies: warp-per-row, LDG.64, bf16-hi output ---------
__device__ __forceinline__ void acc8(float* a, uint2 q0, uint2 q1) {
    float2 f;
    f = __bfloat1622float2(*(__nv_bfloat162*)&q0.x); a[0] += f.x; a[1] += f.y;
    f = __bfloat1622float2(*(__nv_bfloat162*)&q0.y); a[2] += f.x; a[3] += f.y;
    f = __bfloat1622float2(*(__nv_bfloat162*)&q1.x); a[4] += f.x; a[5] += f.y;
    f = __bfloat1622float2(*(__nv_bfloat162*)&q1.y); a[6] += f.x; a[7] += f.y;
}

__device__ __forceinline__ void store_hi8(const float* a, float s,
                                          __nv_bfloat16* out, size_t off) {
    unsigned hq[4];
#pragma unroll
    for (int j = 0; j < 4; j++) {
        __nv_bfloat162 h2 = __floats2bfloat162_rn(a[2*j] * s, a[2*j+1] * s);
        hq[j] = *(unsigned*)&h2;
    }
    *(uint4*)(out + off) = make_uint4(hq[0], hq[1], hq[2], hq[3]);
}

__device__ __forceinline__ void spmm_edges_body(int blk, const uint2* __restrict__ src,
                                                __nv_bfloat16* __restrict__ out) {
    int e    = blk * 8 + (threadIdx.x >> 5);
    int lane = threadIdx.x & 31;
    int craw = g_ccnt[e];
    float se = rsqrtf(fmaxf((float)craw, 1.0f));
    if (lane == 0) g_invse[e] = se;
    int cnt = min(craw, CAP_C);
    const int* lst = &g_rows[e * CAP_C];
    const int lx = lane << 1;
    float a[8];
#pragma unroll
    for (int r = 0; r < 8; r++) a[r] = 0.0f;
    int k = 0;
    for (; k + 4 <= cnt; k += 4) {
        int4 l = *(const int4*)(lst + k);
        const uint2* p0 = src + ((unsigned)l.x << 6) + lx;
        const uint2* p1 = src + ((unsigned)l.y << 6) + lx;
        const uint2* p2 = src + ((unsigned)l.z << 6) + lx;
        const uint2* p3 = src + ((unsigned)l.w << 6) + lx;
        uint2 q00 = p0[0], q01 = p0[1];
        uint2 q10 = p1[0], q11 = p1[1];
        uint2 q20 = p2[0], q21 = p2[1];
        uint2 q30 = p3[0], q31 = p3[1];
        acc8(a, q00, q01); acc8(a, q10, q11); acc8(a, q20, q21); acc8(a, q30, q31);
    }
    for (; k < cnt; k++) {
        const uint2* p0 = src + ((unsigned)lst[k] << 6) + lx;
        acc8(a, p0[0], p0[1]);
    }
    store_hi8(a, se, out, (size_t)e * DIM + lane * 8);
}

__global__ __launch_bounds__(256) void spmm_edges_kernel(const uint2* __restrict__ src,
                                                         __nv_bfloat16* __restrict__ out) {
    spmm_edges_body(blockIdx.x, src, out);
}

__global__ __launch_bounds__(256) void spmm_nodes_kernel(const uint2* __restrict__ src,
                                                         __nv_bfloat16* __restrict__ out) {
    int i    = blockIdx.x * 8 + (threadIdx.x >> 5);
    int lane = threadIdx.x & 31;
    int cnt = g_rcnt[i];
    const int* lst = &g_cols[i * CAP_R];
    const int lx = lane << 1;
    float a[8];
#pragma unroll
    for (int r = 0; r < 8; r++) a[r] = 0.0f;
    int k = 0;
    for (; k + 4 <= cnt; k += 4) {
        int4 l = *(const int4*)(lst + k);
        const uint2* p0 = src + ((unsigned)l.x << 6) + lx;
        const uint2* p1 = src + ((unsigned)l.y << 6) + lx;
        const uint2* p2 = src + ((unsigned)l.z << 6) + lx;
        const uint2* p3 = src + ((unsigned)l.w << 6) + lx;
        uint2 q00 = p0[0], q01 = p0[1];
        uint2 q10 = p1[0], q11 = p1[1];
        uint2 q20 = p2[0], q21 = p2[1];
        uint2 q30 = p3[0], q31 = p3[1];
        acc8(a, q00, q01); acc8(a, q10, q11); acc8(a, q20, q21); acc8(a, q30, q31);
    }
    for (; k < cnt; k++) {
        const uint2* p0 = src + ((unsigned)lst[k] << 6) + lx;
        acc8(a, p0[0], p0[1]);
    }
    float sv = g_invsv[i];
    store_hi8(a, sv, out, (size_t)i * DIM + lane * 8);
}

// ---------------- tensor-core GEMM body: Ah x (Wh+Wl), cp.async 3-stage -----
__device__ __forceinline__ void mma_bf16(float* c, const unsigned* a, const unsigned* b) {
    asm volatile(
        "mma.sync.aligned.m16n8k16.row.col.f32.bf16.bf16.f32 "
        "{%0,%1,%2,%3}, {%4,%5,%6,%7}, {%8,%9}, {%0,%1,%2,%3};\n"
        : "+f"(c[0]), "+f"(c[1]), "+f"(c[2]), "+f"(c[3])
        : "r"(a[0]), "r"(a[1]), "r"(a[2]), "r"(a[3]), "r"(b[0]), "r"(b[1]));
}
__device__ __forceinline__ void ldsm_x4(unsigned* r, unsigned addr) {
    asm volatile("ldmatrix.sync.aligned.m8n8.x4.shared.b16 {%0,%1,%2,%3}, [%4];"
        : "=r"(r[0]), "=r"(r[1]), "=r"(r[2]), "=r"(r[3]) : "r"(addr));
}
__device__ __forceinline__ void ldsm_x4_t(unsigned& r0, unsigned& r1,
                                          unsigned& r2, unsigned& r3, unsigned addr) {
    asm volatile("ldmatrix.sync.aligned.m8n8.x4.trans.shared.b16 {%0,%1,%2,%3}, [%4];"
        : "=r"(r0), "=r"(r1), "=r"(r2), "=r"(r3) : "r"(addr));
}
#define CP_ASYNC16(dst, src) \
    asm volatile("cp.async.cg.shared.global [%0], [%1], 16;" :: "r"(dst), "l"(src))
#define CP_COMMIT() asm volatile("cp.async.commit_group;")
#define CP_WAIT1()  asm volatile("cp.async.wait_group 1;" ::: "memory")

#define ASTG 3072   // 64*48 bytes per A stage
#define BSTG 4352   // 16*272 bytes per B stage per plane

struct GemmSmem {
    unsigned short Ah[3][64][24];
    unsigned short Bh[3][16][136];
    unsigned short Bl[3][16][136];
};

// CTA tile 64(M) x 128(N), KTILE=16, 3 stages; 8 warps 2x4, warp tile 32x32.
template<bool RESID, bool GELU>
__device__ __forceinline__ void gemm_body(
    GemmSmem* gs, int bx, int by,
    const __nv_bfloat16* __restrict__ Ah_g,
    const __nv_bfloat16* __restrict__ Bh_g, const __nv_bfloat16* __restrict__ Bl_g,
    const float* __restrict__ bias, const float* __restrict__ resid,
    const float* __restrict__ gate, float* __restrict__ C,
    __nv_bfloat162* __restrict__ Ch,
    __nv_bfloat162* __restrict__ bfc, const float* __restrict__ rowscale,
    int N, int K)
{
    const int tid  = threadIdx.x;
    const int warp = tid >> 5;
    const int lane = tid & 31;
    const int l15  = lane & 15;
    const int lhi  = lane >> 4;
    const int grp  = lane >> 2;
    const int qd   = lane & 3;
    const int m0 = by * 64;
    const int n0 = bx * 128;
    const int warpM = (warp >> 2) * 32;
    const int warpN = (warp & 3) * 32;

    const unsigned sAh = (unsigned)__cvta_generic_to_shared(&gs->Ah[0][0][0]);
    const unsigned sBh = (unsigned)__cvta_generic_to_shared(&gs->Bh[0][0][0]);
    const unsigned sBl = (unsigned)__cvta_generic_to_shared(&gs->Bl[0][0][0]);

    float acc[2][4][4];
#pragma unroll
    for (int mf = 0; mf < 2; mf++)
#pragma unroll
        for (int nf = 0; nf < 4; nf++)
#pragma unroll
            for (int r = 0; r < 4; r++) acc[mf][nf][r] = 0.0f;

    const int a_m = tid >> 1;
    const int a_c = tid & 1;
    const int b_k = tid >> 4;
    const int b_c = tid & 15;
    const size_t a_goff = (size_t)(m0 + a_m) * K + a_c * 8;
    const size_t b_goff = (size_t)b_k * N + n0 + b_c * 8;
    const unsigned a_soff = a_m * 48 + a_c * 16;
    const unsigned b_soff = b_k * 272 + b_c * 16;
    const bool a_act = (tid < 128);

    auto issue = [&](int s, int k0) {
        if (a_act) CP_ASYNC16(sAh + s * ASTG + a_soff, Ah_g + a_goff + k0);
        CP_ASYNC16(sBh + s * BSTG + b_soff, Bh_g + b_goff + (size_t)k0 * N);
        CP_ASYNC16(sBl + s * BSTG + b_soff, Bl_g + b_goff + (size_t)k0 * N);
    };

    const int ntiles = K / 16;
    issue(0, 0);  CP_COMMIT();
    issue(1, 16); CP_COMMIT();

#pragma unroll 1
    for (int t = 0; t < ntiles; t++) {
        CP_WAIT1();
        __syncthreads();
        if (t + 2 < ntiles) issue((t + 2) % 3, (t + 2) * 16);
        CP_COMMIT();

        const int s = t % 3;
        unsigned afh[2][4], bfh[4][2], bfl[4][2];
#pragma unroll
        for (int mf = 0; mf < 2; mf++) {
            unsigned aoff = (unsigned)s * ASTG
                          + (unsigned)(warpM + mf * 16 + l15) * 48u + (unsigned)lhi * 16u;
            ldsm_x4(afh[mf], sAh + aoff);
        }
#pragma unroll
        for (int p = 0; p < 2; p++) {
            unsigned boff = (unsigned)s * BSTG + (unsigned)l15 * 272u
                          + (unsigned)(warpN + p * 16 + lhi * 8) * 2u;
            ldsm_x4_t(bfh[2*p][0], bfh[2*p][1], bfh[2*p+1][0], bfh[2*p+1][1], sBh + boff);
            ldsm_x4_t(bfl[2*p][0], bfl[2*p][1], bfl[2*p+1][0], bfl[2*p+1][1], sBl + boff);
        }
#pragma unroll
        for (int mf = 0; mf < 2; mf++)
#pragma unroll
            for (int nf = 0; nf < 4; nf++) {
                mma_bf16(acc[mf][nf], afh[mf], bfh[nf]);
                mma_bf16(acc[mf][nf], afh[mf], bfl[nf]);
            }
    }

    float alpha = 1.0f;
    if (!GELU && gate != nullptr) alpha = tanhf(gate[0]);

#pragma unroll
    for (int mf = 0; mf < 2; mf++) {
#pragma unroll
        for (int nf = 0; nf < 4; nf++) {
            int col = n0 + warpN + nf * 8 + 2 * qd;
            float bv0 = bias[col], bv1 = bias[col + 1];
            int r0 = m0 + warpM + mf * 16 + grp;
#pragma unroll
            for (int half = 0; half < 2; half++) {
                int row = r0 + half * 8;
                float v0 = acc[mf][nf][half * 2 + 0] + bv0;
                float v1 = acc[mf][nf][half * 2 + 1] + bv1;
                if (GELU) {
                    v0 = 0.5f * v0 * (1.0f + erff(v0 * 0.7071067811865476f));
                    v1 = 0.5f * v1 * (1.0f + erff(v1 * 0.7071067811865476f));
                } else {
                    v0 *= alpha; v1 *= alpha;
                }
                size_t base = (size_t)row * N + col;
                if (RESID) {
                    float2 r = *(const float2*)(resid + base);
                    v0 += r.x; v1 += r.y;
                }
                if (C) *(float2*)(C + base) = make_float2(v0, v1);
                if (Ch) Ch[base >> 1] = __floats2bfloat162_rn(v0, v1);
                if (bfc) {
                    float s = rowscale ? rowscale[row] : 1.0f;
                    bfc[base >> 1] = __floats2bfloat162_rn(v0 * s, v1 * s);
                }
            }
        }
    }
}

// Standalone GEMM kernel (steps 4, 6)
template<bool RESID, bool GELU>
__global__ __launch_bounds__(256, 2) void gemm_tc_kernel(
    const __nv_bfloat16* __restrict__ Ah_g,
    const __nv_bfloat16* __restrict__ Bh_g, const __nv_bfloat16* __restrict__ Bl_g,
    const float* __restrict__ bias, const float* __restrict__ resid,
    const float* __restrict__ gate, float* __restrict__ C,
    __nv_bfloat162* __restrict__ Ch,
    __nv_bfloat162* __restrict__ bfc, const float* __restrict__ rowscale,
    int N, int K)
{
    __shared__ GemmSmem gs;
    gemm_body<RESID, GELU>(&gs, blockIdx.x, blockIdx.y,
                           Ah_g, Bh_g, Bl_g, bias, resid, gate, C, Ch, bfc, rowscale,
                           N, K);
}

// Fused A: even blocks = ret-SpMM (1024), odd blocks = FFN1 GEMM (1024)
__global__ __launch_bounds__(256, 2) void fused_a_kernel(const float* __restrict__ b1) {
    __shared__ GemmSmem gs;
    int b = blockIdx.x;
    if ((b & 1) == 0) {
        spmm_edges_body(b >> 1, (const uint2*)g_x0lbf, g_reth);
    } else {
        int id = b >> 1;               // 0..1023 -> grid (4, 256)
        gemm_body<false, true>(&gs, id & 3, id >> 2,
                               g_x0gh, g_wh + OFF_W1, g_wl + OFF_W1, b1,
                               nullptr, nullptr, nullptr,
                               (__nv_bfloat162*)g_hh, nullptr, nullptr,
                               2 * DIM, DIM);
    }
}

// Fused B: b%3==0 -> x1_out GEMM (256), else -> FFN2 GEMM (512)
__global__ __launch_bounds__(256, 2) void fused_b_kernel(
    const float* __restrict__ br, const float* __restrict__ gr,
    float* __restrict__ out_x1,
    const float* __restrict__ b2, float* __restrict__ out_x0)
{
    __shared__ GemmSmem gs;
    int b = blockIdx.x;
    if (b % 3 == 0) {
        int id = b / 3;                // 0..255 -> grid (2, 128)
        gemm_body<true, false>(&gs, id & 1, id >> 1,
                               g_reth, g_wh + OFF_WR, g_wl + OFF_WR, br,
                               g_x1a, gr, out_x1, nullptr, nullptr, nullptr,
                               DIM, DIM);
    } else {
        int id = b - b / 3 - 1;        // 0..511 -> grid (2, 256)
        gemm_body<true, false>(&gs, id & 1, id >> 1,
                               g_hh, g_wh + OFF_W2, g_wl + OFF_W2, b2,
                               g_x0g, nullptr, out_x0, nullptr, nullptr, nullptr,
                               DIM, 2 * DIM);
    }
}

// ---------------- fused double LayerNorm -------------------------------------
__device__ __forceinline__ float block_sum_256(float v, float* sm) {
#pragma unroll
    for (int o = 16; o > 0; o >>= 1) v += __shfl_xor_sync(0xffffffffu, v, o);
    int w = threadIdx.x >> 5, lane = threadIdx.x & 31;
    if (lane == 0) sm[w] = v;
    __syncthreads();
    if (w == 0) {
        float s = (lane < 8) ? sm[lane] : 0.0f;
#pragma unroll
        for (int o = 4; o > 0; o >>= 1) s += __shfl_xor_sync(0xffffffffu, s, o);
        if (lane == 0) sm[0] = s;
    }
    __syncthreads();
    float r = sm[0];
    __syncthreads();
    return r;
}

__global__ __launch_bounds__(DIM) void ln_double_kernel(
    const float* __restrict__ g1, const float* __restrict__ b1,
    const float* __restrict__ g2, const float* __restrict__ b2)
{
    __shared__ float sm[8];
    int r = blockIdx.x, t = threadIdx.x;
    size_t idx = (size_t)r * DIM + t;
    float v = g_u[idx];
    float mean = block_sum_256(v, sm) * (1.0f / DIM);
    float d = v - mean;
    float var = block_sum_256(d * d, sm) * (1.0f / DIM);
    float y = d * rsqrtf(var + LN_EPS) * g1[t] + b1[t];
    {
        float sv = g_invsv[r];
        float y_hi = __shfl_xor_sync(0xffffffffu, y, 1);
        if ((t & 1) == 0)
            g_x0lbf[idx >> 1] = __floats2bfloat162_rn(y * sv, y_hi * sv);
    }
    float m2 = block_sum_256(y, sm) * (1.0f / DIM);
    float d2 = y - m2;
    float v2 = block_sum_256(d2 * d2, sm) * (1.0f / DIM);
    float z = d2 * rsqrtf(v2 + LN_EPS) * g2[t] + b2[t];
    g_x0g[idx] = z;
    {
        float z_n = __shfl_xor_sync(0xffffffffu, z, 1);
        if ((t & 1) == 0) {
            __nv_bfloat162 h2 = __floats2bfloat162_rn(z, z_n);
            ((unsigned*)g_x0gh)[idx >> 1] = *(unsigned*)&h2;
        }
    }
}

// ---------------- driver -----------------------------------------------------
extern "C" void kernel_launch(void* const* d_in, const int* in_sizes, int n_in,
                              void* d_out, int out_size) {
    const float* x0   = (const float*)d_in[0];
    const float* x1   = (const float*)d_in[1];
    const float* H    = (const float*)d_in[2];
    const float* Wn   = (const float*)d_in[3];
    const float* bn   = (const float*)d_in[4];
    const float* We   = (const float*)d_in[5];
    const float* be   = (const float*)d_in[6];
    const float* Wr   = (const float*)d_in[7];
    const float* br   = (const float*)d_in[8];
    const float* W1   = (const float*)d_in[9];
    const float* b1   = (const float*)d_in[10];
    const float* W2   = (const float*)d_in[11];
    const float* b2   = (const float*)d_in[12];
    const float* ln1g = (const float*)d_in[13];
    const float* ln1b = (const float*)d_in[14];
    const float* ln2g = (const float*)d_in[15];
    const float* ln2b = (const float*)d_in[16];
    const float* gl   = (const float*)d_in[17];
    const float* gr   = (const float*)d_in[18];

    float* out_x0 = (float*)d_out;
    float* out_x1 = (float*)d_out + (size_t)NN * DIM;

    float *p_x1a, *p_u, *p_invse;
    __nv_bfloat162 *p_x0bf, *p_x1abf;
    __nv_bfloat16 *p_wh, *p_wl, *p_tmpEh, *p_msgh;
    cudaGetSymbolAddress((void**)&p_x1a,  g_x1a);
    cudaGetSymbolAddress((void**)&p_u,    g_u);
    cudaGetSymbolAddress((void**)&p_invse, g_invse);
    cudaGetSymbolAddress((void**)&p_x0bf,  g_x0bf);
    cudaGetSymbolAddress((void**)&p_x1abf, g_x1abf);
    cudaGetSymbolAddress((void**)&p_wh, g_wh);
    cudaGetSymbolAddress((void**)&p_wl, g_wl);
    cudaGetSymbolAddress((void**)&p_tmpEh, g_tmpEh);
    cudaGetSymbolAddress((void**)&p_msgh, g_msgh);

    // 1) sparse build + weight prepack (fused, DRAM-bound)
    build_csr_kernel<<<NN / 8, 256>>>(H, We, Wn, Wr, W1, W2);
    // 2) scatter + x0->bf16(*invsv)
    scatter_cvt_kernel<<<(NN * CAP_R) / 256, 256>>>(x0);
    // 3) tmpE = H_norm^T @ x0 -> bf16-hi plane (publishes invse)
    spmm_edges_kernel<<<EE / 8, 256>>>((const uint2*)p_x0bf, p_tmpEh);
    // 4) x1a = x1 + tmpE @ We + be (fp32 + gather copy)   <-- ncu profiled slot
    gemm_tc_kernel<true, false><<<dim3(DIM / 128, EE / 64), 256>>>(
        p_tmpEh, p_wh + OFF_WE, p_wl + OFF_WE, be, x1, nullptr, p_x1a,
        nullptr, p_x1abf, p_invse, DIM, DIM);
    // 5) msg = H_norm @ x1a -> bf16-hi plane
    spmm_nodes_kernel<<<NN / 8, 256>>>((const uint2*)p_x1abf, p_msgh);
    // 6) u = x0 + tanh(gl) * (msg @ Wn + bn)
    gemm_tc_kernel<true, false><<<dim3(DIM / 128, NN / 64), 256>>>(
        p_msgh, p_wh + OFF_WN, p_wl + OFF_WN, bn, x0, gl, p_u,
        nullptr, nullptr, nullptr, DIM, DIM);
    // 7) LN1 (gather copy) + LN2 (fp32 + bf16-hi plane)
    ln_double_kernel<<<NN, DIM>>>(ln1g, ln1b, ln2g, ln2b);
    // 8+10) fused: ret = H_norm^T @ x0_local  ||  h = gelu(x0g @ W1 + b1)
    fused_a_kernel<<<2 * 1024, 256>>>(b1);
    // 9+11) fused: x1_out = x1a + tanh(gr)*(ret @ Wr + br) || x0_out = x0g + h @ W2 + b2
    fused_b_kernel<<<768, 256>>>(br, gr, out_x1, b2, out_x0);

    (void)in_sizes; (void)n_in; (void)out_size;
}

// round 15
// speedup vs baseline: 1.0615x; 1.0615x over previous
#include <cuda_runtime.h>
#include <cuda_bf16.h>
#include <math.h>

// Problem constants
#define NN   16384
#define EE   8192
#define DIM  256
#define CAP_R 128
#define CAP_C 192
#define LN_EPS 1e-5f

// Weight-plane offsets (elements) inside g_wh / g_wl ([K][N] layout)
#define OFF_WE 0
#define OFF_WN 65536
#define OFF_WR 131072
#define OFF_W1 196608
#define OFF_W2 327680
#define W_TOTAL 458752

// ---------------- static device scratch (no allocations allowed) ------------
__device__ int   g_cols[NN * CAP_R];
__device__ int   g_rows[EE * CAP_C];
__device__ int   g_rcnt[NN];
__device__ int   g_ccnt[EE];
__device__ float g_invsv[NN];
__device__ float g_invse[EE];

__device__ float g_x1a [EE * DIM];
__device__ float g_u   [NN * DIM];
__device__ float g_x0g [NN * DIM];

// bf16 gather sources for the SpMMs (pre-scaled; 16B-aligned for LDG.128)
__device__ __align__(16) __nv_bfloat162 g_x0bf [NN * DIM / 2];
__device__ __align__(16) __nv_bfloat162 g_x1abf[EE * DIM / 2];
__device__ __align__(16) __nv_bfloat162 g_x0lbf[NN * DIM / 2];

// bf16 planes for GEMM A operands (hi only; produced by upstream kernels)
__device__ __align__(16) __nv_bfloat16 g_tmpEh[EE * DIM];
__device__ __align__(16) __nv_bfloat16 g_msgh [NN * DIM];
__device__ __align__(16) __nv_bfloat16 g_reth [EE * DIM];
__device__ __align__(16) __nv_bfloat16 g_x0gh [NN * DIM];
__device__ __align__(16) __nv_bfloat16 g_hh   [NN * 2 * DIM];

// pre-split bf16 hi/lo weight planes ([K][N])
__device__ __align__(16) __nv_bfloat16 g_wh[W_TOTAL];
__device__ __align__(16) __nv_bfloat16 g_wl[W_TOTAL];

// ---------------- sparse build + weight prepack (fused; DRAM-bound) ---------
__global__ __launch_bounds__(256) void build_csr_kernel(
    const float* __restrict__ H,
    const float* __restrict__ We, const float* __restrict__ Wn,
    const float* __restrict__ Wr, const float* __restrict__ W1,
    const float* __restrict__ W2)
{
    int gtid = blockIdx.x * blockDim.x + threadIdx.x;
    if (gtid < EE) g_ccnt[gtid] = 0;
    if (gtid < W_TOTAL) {
        const float* src; int off;
        if      (gtid < OFF_WN) { src = We; off = OFF_WE; }
        else if (gtid < OFF_WR) { src = Wn; off = OFF_WN; }
        else if (gtid < OFF_W1) { src = Wr; off = OFF_WR; }
        else if (gtid < OFF_W2) { src = W1; off = OFF_W1; }
        else                    { src = W2; off = OFF_W2; }
        float v = src[gtid - off];
        __nv_bfloat16 h = __float2bfloat16_rn(v);
        g_wh[gtid] = h;
        g_wl[gtid] = __float2bfloat16_rn(v - __bfloat162float(h));
    }

    int warp = gtid >> 5;
    int lane = threadIdx.x & 31;
    if (warp >= NN) return;
    const float* row = H + (size_t)warp * EE;
    int base = 0;
    for (int it = 0; it < EE / 128; it++) {
        float4 v4 = *(const float4*)(row + it * 128 + lane * 4);
        float v[4] = {v4.x, v4.y, v4.z, v4.w};
#pragma unroll
        for (int j = 0; j < 4; j++) {
            unsigned m = __ballot_sync(0xffffffffu, v[j] != 0.0f);
            if (v[j] != 0.0f) {
                int pos = base + __popc(m & ((1u << lane) - 1u));
                if (pos < CAP_R) g_cols[warp * CAP_R + pos] = it * 128 + lane * 4 + j;
            }
            base += __popc(m);
        }
    }
    if (lane == 0) {
        g_rcnt[warp]  = min(base, CAP_R);
        g_invsv[warp] = rsqrtf(fmaxf((float)base, 1.0f));
    }
}

// Fused: CSR->CSC scatter + x0 -> bf16 (pre-scaled by invsv[row]).
__global__ void scatter_cvt_kernel(const float* __restrict__ x0) {
    int tid = blockIdx.x * blockDim.x + threadIdx.x;
    int row = tid >> 7;
    float2 p = *(const float2*)(x0 + (size_t)tid * 2);
    float s = g_invsv[row];
    g_x0bf[tid] = __floats2bfloat162_rn(p.x * s, p.y * s);

    int k = tid & (CAP_R - 1);
    if (k < g_rcnt[row]) {
        int col = g_cols[row * CAP_R + k];
        int p2 = atomicAdd(&g_ccnt[col], 1);
        if (p2 < CAP_C) g_rows[col * CAP_C + p2] = row;
    }
}

// ---------------- SpMM gathers: warp-per-row, LDG.128, bf16-hi output -------
__device__ __forceinline__ void acc8q(float* a, uint4 q) {
    float2 f;
    f = __bfloat1622float2(*(__nv_bfloat162*)&q.x); a[0] += f.x; a[1] += f.y;
    f = __bfloat1622float2(*(__nv_bfloat162*)&q.y); a[2] += f.x; a[3] += f.y;
    f = __bfloat1622float2(*(__nv_bfloat162*)&q.z); a[4] += f.x; a[5] += f.y;
    f = __bfloat1622float2(*(__nv_bfloat162*)&q.w); a[6] += f.x; a[7] += f.y;
}

__device__ __forceinline__ void store_hi8(const float* a, float s,
                                          __nv_bfloat16* out, size_t off) {
    unsigned hq[4];
#pragma unroll
    for (int j = 0; j < 4; j++) {
        __nv_bfloat162 h2 = __floats2bfloat162_rn(a[2*j] * s, a[2*j+1] * s);
        hq[j] = *(unsigned*)&h2;
    }
    *(uint4*)(out + off) = make_uint4(hq[0], hq[1], hq[2], hq[3]);
}

// src viewed as uint4: 32 per row (256 dims * 2B = 512B); lane owns one uint4.
__global__ __launch_bounds__(256) void spmm_edges_kernel(const uint4* __restrict__ src,
                                                         __nv_bfloat16* __restrict__ out) {
    int e    = blockIdx.x * 8 + (threadIdx.x >> 5);
    int lane = threadIdx.x & 31;
    int craw = g_ccnt[e];
    float se = rsqrtf(fmaxf((float)craw, 1.0f));
    if (lane == 0) g_invse[e] = se;
    int cnt = min(craw, CAP_C);
    const int* lst = &g_rows[e * CAP_C];
    float a[8];
#pragma unroll
    for (int r = 0; r < 8; r++) a[r] = 0.0f;
    int k = 0;
    for (; k + 4 <= cnt; k += 4) {
        int4 l = *(const int4*)(lst + k);
        uint4 q0 = src[((unsigned)l.x << 5) + lane];
        uint4 q1 = src[((unsigned)l.y << 5) + lane];
        uint4 q2 = src[((unsigned)l.z << 5) + lane];
        uint4 q3 = src[((unsigned)l.w << 5) + lane];
        acc8q(a, q0); acc8q(a, q1); acc8q(a, q2); acc8q(a, q3);
    }
    for (; k < cnt; k++) {
        acc8q(a, src[((unsigned)lst[k] << 5) + lane]);
    }
    store_hi8(a, se, out, (size_t)e * DIM + lane * 8);
}

__global__ __launch_bounds__(256) void spmm_nodes_kernel(const uint4* __restrict__ src,
                                                         __nv_bfloat16* __restrict__ out) {
    int i    = blockIdx.x * 8 + (threadIdx.x >> 5);
    int lane = threadIdx.x & 31;
    int cnt = g_rcnt[i];
    const int* lst = &g_cols[i * CAP_R];
    float a[8];
#pragma unroll
    for (int r = 0; r < 8; r++) a[r] = 0.0f;
    int k = 0;
    for (; k + 4 <= cnt; k += 4) {
        int4 l = *(const int4*)(lst + k);
        uint4 q0 = src[((unsigned)l.x << 5) + lane];
        uint4 q1 = src[((unsigned)l.y << 5) + lane];
        uint4 q2 = src[((unsigned)l.z << 5) + lane];
        uint4 q3 = src[((unsigned)l.w << 5) + lane];
        acc8q(a, q0); acc8q(a, q1); acc8q(a, q2); acc8q(a, q3);
    }
    for (; k < cnt; k++) {
        acc8q(a, src[((unsigned)lst[k] << 5) + lane]);
    }
    float sv = g_invsv[i];
    store_hi8(a, sv, out, (size_t)i * DIM + lane * 8);
}

// ---------------- tensor-core GEMM: Ah x (Wh+Wl), cp.async 3-stage ----------
__device__ __forceinline__ void mma_bf16(float* c, const unsigned* a, const unsigned* b) {
    asm volatile(
        "mma.sync.aligned.m16n8k16.row.col.f32.bf16.bf16.f32 "
        "{%0,%1,%2,%3}, {%4,%5,%6,%7}, {%8,%9}, {%0,%1,%2,%3};\n"
        : "+f"(c[0]), "+f"(c[1]), "+f"(c[2]), "+f"(c[3])
        : "r"(a[0]), "r"(a[1]), "r"(a[2]), "r"(a[3]), "r"(b[0]), "r"(b[1]));
}
__device__ __forceinline__ void ldsm_x4(unsigned* r, unsigned addr) {
    asm volatile("ldmatrix.sync.aligned.m8n8.x4.shared.b16 {%0,%1,%2,%3}, [%4];"
        : "=r"(r[0]), "=r"(r[1]), "=r"(r[2]), "=r"(r[3]) : "r"(addr));
}
__device__ __forceinline__ void ldsm_x4_t(unsigned& r0, unsigned& r1,
                                          unsigned& r2, unsigned& r3, unsigned addr) {
    asm volatile("ldmatrix.sync.aligned.m8n8.x4.trans.shared.b16 {%0,%1,%2,%3}, [%4];"
        : "=r"(r0), "=r"(r1), "=r"(r2), "=r"(r3) : "r"(addr));
}
#define CP_ASYNC16(dst, src) \
    asm volatile("cp.async.cg.shared.global [%0], [%1], 16;" :: "r"(dst), "l"(src))
#define CP_COMMIT() asm volatile("cp.async.commit_group;")
#define CP_WAIT1()  asm volatile("cp.async.wait_group 1;" ::: "memory")

// CTA tile 64(M) x 128(N), KTILE=16, 3 smem stages (static).
// 8 warps 2(M) x 4(N); warp tile 32x32; 16 MMAs per warp per k-tile.
// A smem: ushort [64][24] (48B pitch).  B smem: k-major ushort [16][136] (272B pitch).
#define ASTG 3072   // 64*48
#define BSTG 4352   // 16*272

template<bool RESID, bool GELU>
__global__ __launch_bounds__(256, 2) void gemm_tc_kernel(
    const __nv_bfloat16* __restrict__ Ah_g,
    const __nv_bfloat16* __restrict__ Bh_g, const __nv_bfloat16* __restrict__ Bl_g,
    const float* __restrict__ bias, const float* __restrict__ resid,
    const float* __restrict__ gate, float* __restrict__ C,
    __nv_bfloat162* __restrict__ Ch,
    __nv_bfloat162* __restrict__ bfc, const float* __restrict__ rowscale,
    int M, int N, int K)
{
    __shared__ __align__(16) unsigned short Ahs[3][64][24];
    __shared__ __align__(16) unsigned short Bhs[3][16][136];
    __shared__ __align__(16) unsigned short Bls[3][16][136];

    const int tid  = threadIdx.x;
    const int warp = tid >> 5;
    const int lane = tid & 31;
    const int l15  = lane & 15;
    const int lhi  = lane >> 4;
    const int grp  = lane >> 2;
    const int qd   = lane & 3;
    const int m0 = blockIdx.y * 64;
    const int n0 = blockIdx.x * 128;
    const int warpM = (warp >> 2) * 32;
    const int warpN = (warp & 3) * 32;

    const unsigned sAh = (unsigned)__cvta_generic_to_shared(&Ahs[0][0][0]);
    const unsigned sBh = (unsigned)__cvta_generic_to_shared(&Bhs[0][0][0]);
    const unsigned sBl = (unsigned)__cvta_generic_to_shared(&Bls[0][0][0]);

    float acc[2][4][4];
#pragma unroll
    for (int mf = 0; mf < 2; mf++)
#pragma unroll
        for (int nf = 0; nf < 4; nf++)
#pragma unroll
            for (int r = 0; r < 4; r++) acc[mf][nf][r] = 0.0f;

    const int a_m = tid >> 1;
    const int a_c = tid & 1;
    const int b_k = tid >> 4;
    const int b_c = tid & 15;
    const size_t a_goff = (size_t)(m0 + a_m) * K + a_c * 8;
    const size_t b_goff = (size_t)b_k * N + n0 + b_c * 8;
    const unsigned a_soff = a_m * 48 + a_c * 16;
    const unsigned b_soff = b_k * 272 + b_c * 16;
    const bool a_act = (tid < 128);

    auto issue = [&](int s, int k0) {
        if (a_act) CP_ASYNC16(sAh + s * ASTG + a_soff, Ah_g + a_goff + k0);
        CP_ASYNC16(sBh + s * BSTG + b_soff, Bh_g + b_goff + (size_t)k0 * N);
        CP_ASYNC16(sBl + s * BSTG + b_soff, Bl_g + b_goff + (size_t)k0 * N);
    };

    const int ntiles = K / 16;
    issue(0, 0);  CP_COMMIT();
    issue(1, 16); CP_COMMIT();

#pragma unroll 1
    for (int t = 0; t < ntiles; t++) {
        CP_WAIT1();
        __syncthreads();
        if (t + 2 < ntiles) issue((t + 2) % 3, (t + 2) * 16);
        CP_COMMIT();

        const int s = t % 3;
        unsigned afh[2][4], bfh[4][2], bfl[4][2];
#pragma unroll
        for (int mf = 0; mf < 2; mf++) {
            unsigned aoff = (unsigned)s * ASTG
                          + (unsigned)(warpM + mf * 16 + l15) * 48u + (unsigned)lhi * 16u;
            ldsm_x4(afh[mf], sAh + aoff);
        }
#pragma unroll
        for (int p = 0; p < 2; p++) {
            unsigned boff = (unsigned)s * BSTG + (unsigned)l15 * 272u
                          + (unsigned)(warpN + p * 16 + lhi * 8) * 2u;
            ldsm_x4_t(bfh[2*p][0], bfh[2*p][1], bfh[2*p+1][0], bfh[2*p+1][1], sBh + boff);
            ldsm_x4_t(bfl[2*p][0], bfl[2*p][1], bfl[2*p+1][0], bfl[2*p+1][1], sBl + boff);
        }
#pragma unroll
        for (int mf = 0; mf < 2; mf++)
#pragma unroll
            for (int nf = 0; nf < 4; nf++) {
                mma_bf16(acc[mf][nf], afh[mf], bfh[nf]);
                mma_bf16(acc[mf][nf], afh[mf], bfl[nf]);
            }
    }

    float alpha = 1.0f;
    if (!GELU && gate != nullptr) alpha = tanhf(gate[0]);

#pragma unroll
    for (int mf = 0; mf < 2; mf++) {
#pragma unroll
        for (int nf = 0; nf < 4; nf++) {
            int col = n0 + warpN + nf * 8 + 2 * qd;
            float bv0 = bias[col], bv1 = bias[col + 1];
            int r0 = m0 + warpM + mf * 16 + grp;
#pragma unroll
            for (int half = 0; half < 2; half++) {
                int row = r0 + half * 8;
                float v0 = acc[mf][nf][half * 2 + 0] + bv0;
                float v1 = acc[mf][nf][half * 2 + 1] + bv1;
                if (GELU) {
                    v0 = 0.5f * v0 * (1.0f + erff(v0 * 0.7071067811865476f));
                    v1 = 0.5f * v1 * (1.0f + erff(v1 * 0.7071067811865476f));
                } else {
                    v0 *= alpha; v1 *= alpha;
                }
                size_t base = (size_t)row * N + col;
                if (RESID) {
                    float2 r = *(const float2*)(resid + base);
                    v0 += r.x; v1 += r.y;
                }
                if (C) *(float2*)(C + base) = make_float2(v0, v1);
                if (Ch) Ch[base >> 1] = __floats2bfloat162_rn(v0, v1);
                if (bfc) {
                    float s = rowscale ? rowscale[row] : 1.0f;
                    bfc[base >> 1] = __floats2bfloat162_rn(v0 * s, v1 * s);
                }
            }
        }
    }
}

// ---------------- fused double LayerNorm -------------------------------------
__device__ __forceinline__ float block_sum_256(float v, float* sm) {
#pragma unroll
    for (int o = 16; o > 0; o >>= 1) v += __shfl_xor_sync(0xffffffffu, v, o);
    int w = threadIdx.x >> 5, lane = threadIdx.x & 31;
    if (lane == 0) sm[w] = v;
    __syncthreads();
    if (w == 0) {
        float s = (lane < 8) ? sm[lane] : 0.0f;
#pragma unroll
        for (int o = 4; o > 0; o >>= 1) s += __shfl_xor_sync(0xffffffffu, s, o);
        if (lane == 0) sm[0] = s;
    }
    __syncthreads();
    float r = sm[0];
    __syncthreads();
    return r;
}

__global__ __launch_bounds__(DIM) void ln_double_kernel(
    const float* __restrict__ g1, const float* __restrict__ b1,
    const float* __restrict__ g2, const float* __restrict__ b2)
{
    __shared__ float sm[8];
    int r = blockIdx.x, t = threadIdx.x;
    size_t idx = (size_t)r * DIM + t;
    float v = g_u[idx];
    float mean = block_sum_256(v, sm) * (1.0f / DIM);
    float d = v - mean;
    float var = block_sum_256(d * d, sm) * (1.0f / DIM);
    float y = d * rsqrtf(var + LN_EPS) * g1[t] + b1[t];
    {
        float sv = g_invsv[r];
        float y_hi = __shfl_xor_sync(0xffffffffu, y, 1);
        if ((t & 1) == 0)
            g_x0lbf[idx >> 1] = __floats2bfloat162_rn(y * sv, y_hi * sv);
    }
    float m2 = block_sum_256(y, sm) * (1.0f / DIM);
    float d2 = y - m2;
    float v2 = block_sum_256(d2 * d2, sm) * (1.0f / DIM);
    float z = d2 * rsqrtf(v2 + LN_EPS) * g2[t] + b2[t];
    g_x0g[idx] = z;
    {
        float z_n = __shfl_xor_sync(0xffffffffu, z, 1);
        if ((t & 1) == 0) {
            __nv_bfloat162 h2 = __floats2bfloat162_rn(z, z_n);
            ((unsigned*)g_x0gh)[idx >> 1] = *(unsigned*)&h2;
        }
    }
}

// ---------------- driver -----------------------------------------------------
extern "C" void kernel_launch(void* const* d_in, const int* in_sizes, int n_in,
                              void* d_out, int out_size) {
    const float* x0   = (const float*)d_in[0];
    const float* x1   = (const float*)d_in[1];
    const float* H    = (const float*)d_in[2];
    const float* Wn   = (const float*)d_in[3];
    const float* bn   = (const float*)d_in[4];
    const float* We   = (const float*)d_in[5];
    const float* be   = (const float*)d_in[6];
    const float* Wr   = (const float*)d_in[7];
    const float* br   = (const float*)d_in[8];
    const float* W1   = (const float*)d_in[9];
    const float* b1   = (const float*)d_in[10];
    const float* W2   = (const float*)d_in[11];
    const float* b2   = (const float*)d_in[12];
    const float* ln1g = (const float*)d_in[13];
    const float* ln1b = (const float*)d_in[14];
    const float* ln2g = (const float*)d_in[15];
    const float* ln2b = (const float*)d_in[16];
    const float* gl   = (const float*)d_in[17];
    const float* gr   = (const float*)d_in[18];

    float* out_x0 = (float*)d_out;
    float* out_x1 = (float*)d_out + (size_t)NN * DIM;

    float *p_x1a, *p_u, *p_x0g, *p_invse;
    __nv_bfloat162 *p_x0bf, *p_x1abf, *p_x0lbf;
    __nv_bfloat16 *p_wh, *p_wl;
    __nv_bfloat16 *p_tmpEh, *p_msgh, *p_reth, *p_x0gh, *p_hh;
    cudaGetSymbolAddress((void**)&p_x1a,  g_x1a);
    cudaGetSymbolAddress((void**)&p_u,    g_u);
    cudaGetSymbolAddress((void**)&p_x0g,  g_x0g);
    cudaGetSymbolAddress((void**)&p_invse, g_invse);
    cudaGetSymbolAddress((void**)&p_x0bf,  g_x0bf);
    cudaGetSymbolAddress((void**)&p_x1abf, g_x1abf);
    cudaGetSymbolAddress((void**)&p_x0lbf, g_x0lbf);
    cudaGetSymbolAddress((void**)&p_wh, g_wh);
    cudaGetSymbolAddress((void**)&p_wl, g_wl);
    cudaGetSymbolAddress((void**)&p_tmpEh, g_tmpEh);
    cudaGetSymbolAddress((void**)&p_msgh, g_msgh);
    cudaGetSymbolAddress((void**)&p_reth, g_reth);
    cudaGetSymbolAddress((void**)&p_x0gh, g_x0gh);
    cudaGetSymbolAddress((void**)&p_hh, g_hh);

    // 1) sparse build + weight prepack (fused, DRAM-bound)
    build_csr_kernel<<<NN / 8, 256>>>(H, We, Wn, Wr, W1, W2);
    // 2) scatter + x0->bf16(*invsv)
    scatter_cvt_kernel<<<(NN * CAP_R) / 256, 256>>>(x0);
    // 3) tmpE = H_norm^T @ x0 -> bf16-hi plane (publishes invse)
    spmm_edges_kernel<<<EE / 8, 256>>>((const uint4*)p_x0bf, p_tmpEh);
    // 4) x1a = x1 + tmpE @ We + be (fp32 + gather copy)   <-- ncu profiled slot
    gemm_tc_kernel<true, false><<<dim3(DIM / 128, EE / 64), 256>>>(
        p_tmpEh, p_wh + OFF_WE, p_wl + OFF_WE, be, x1, nullptr, p_x1a,
        nullptr, p_x1abf, p_invse, EE, DIM, DIM);
    // 5) msg = H_norm @ x1a -> bf16-hi plane
    spmm_nodes_kernel<<<NN / 8, 256>>>((const uint4*)p_x1abf, p_msgh);
    // 6) u = x0 + tanh(gl) * (msg @ Wn + bn)
    gemm_tc_kernel<true, false><<<dim3(DIM / 128, NN / 64), 256>>>(
        p_msgh, p_wh + OFF_WN, p_wl + OFF_WN, bn, x0, gl, p_u,
        nullptr, nullptr, nullptr, NN, DIM, DIM);
    // 7) LN1 (gather copy) + LN2 (fp32 + bf16-hi plane)
    ln_double_kernel<<<NN, DIM>>>(ln1g, ln1b, ln2g, ln2b);
    // 8) ret = H_norm^T @ x0_local -> bf16-hi plane
    spmm_edges_kernel<<<EE / 8, 256>>>((const uint4*)p_x0lbf, p_reth);
    // 9) x1_out = x1a + tanh(gr) * (ret @ Wr + br)
    gemm_tc_kernel<true, false><<<dim3(DIM / 128, EE / 64), 256>>>(
        p_reth, p_wh + OFF_WR, p_wl + OFF_WR, br, p_x1a, gr, out_x1,
        nullptr, nullptr, nullptr, EE, DIM, DIM);
    // 10) h = gelu(x0_global @ W1 + b1) -> bf16-hi plane only
    gemm_tc_kernel<false, true><<<dim3((2 * DIM) / 128, NN / 64), 256>>>(
        p_x0gh, p_wh + OFF_W1, p_wl + OFF_W1, b1, nullptr, nullptr, nullptr,
        (__nv_bfloat162*)p_hh, nullptr, nullptr, NN, 2 * DIM, DIM);
    // 11) x0_out = x0_global + h @ W2 + b2   (K = 512)
    gemm_tc_kernel<true, false><<<dim3(DIM / 128, NN / 64), 256>>>(
        p_hh, p_wh + OFF_W2, p_wl + OFF_W2, b2, p_x0g, nullptr, out_x0,
        nullptr, nullptr, nullptr, NN, DIM, 2 * DIM);

    (void)in_sizes; (void)n_in; (void)out_size;
}

// round 16
// speedup vs baseline: 1.0795x; 1.0170x over previous
#include <cuda_runtime.h>
#include <cuda_bf16.h>
#include <math.h>

// Problem constants
#define NN   16384
#define EE   8192
#define DIM  256
#define CAP_R 128
#define CAP_C 192
#define LN_EPS 1e-5f

// Weight-plane offsets (elements) inside g_wh / g_wl ([K][N] layout)
#define OFF_WE 0
#define OFF_WN 65536
#define OFF_WR 131072
#define OFF_W1 196608
#define OFF_W2 327680
#define W_TOTAL 458752

// ---------------- static device scratch (no allocations allowed) ------------
__device__ int   g_cols[NN * CAP_R];
__device__ int   g_rows[EE * CAP_C];
__device__ int   g_rcnt[NN];
__device__ int   g_ccnt[EE];
__device__ float g_invsv[NN];
__device__ float g_invse[EE];

__device__ float g_x1a [EE * DIM];
__device__ float g_u   [NN * DIM];
__device__ float g_x0g [NN * DIM];

// bf16 gather sources for the SpMMs (pre-scaled; 16B-aligned for LDG.128)
__device__ __align__(16) __nv_bfloat162 g_x0bf [NN * DIM / 2];
__device__ __align__(16) __nv_bfloat162 g_x1abf[EE * DIM / 2];
__device__ __align__(16) __nv_bfloat162 g_x0lbf[NN * DIM / 2];

// bf16 planes for GEMM A operands (hi only; produced by upstream kernels)
__device__ __align__(16) __nv_bfloat16 g_tmpEh[EE * DIM];
__device__ __align__(16) __nv_bfloat16 g_msgh [NN * DIM];
__device__ __align__(16) __nv_bfloat16 g_reth [EE * DIM];
__device__ __align__(16) __nv_bfloat16 g_x0gh [NN * DIM];
__device__ __align__(16) __nv_bfloat16 g_hh   [NN * 2 * DIM];

// pre-split bf16 hi/lo weight planes ([K][N])
__device__ __align__(16) __nv_bfloat16 g_wh[W_TOTAL];
__device__ __align__(16) __nv_bfloat16 g_wl[W_TOTAL];

// ---------------- sparse build + weight prepack (fused; DRAM-bound) ---------
__global__ __launch_bounds__(256) void build_csr_kernel(
    const float* __restrict__ H,
    const float* __restrict__ We, const float* __restrict__ Wn,
    const float* __restrict__ Wr, const float* __restrict__ W1,
    const float* __restrict__ W2)
{
    int gtid = blockIdx.x * blockDim.x + threadIdx.x;
    if (gtid < EE) g_ccnt[gtid] = 0;
    if (gtid < W_TOTAL) {
        const float* src; int off;
        if      (gtid < OFF_WN) { src = We; off = OFF_WE; }
        else if (gtid < OFF_WR) { src = Wn; off = OFF_WN; }
        else if (gtid < OFF_W1) { src = Wr; off = OFF_WR; }
        else if (gtid < OFF_W2) { src = W1; off = OFF_W1; }
        else                    { src = W2; off = OFF_W2; }
        float v = src[gtid - off];
        __nv_bfloat16 h = __float2bfloat16_rn(v);
        g_wh[gtid] = h;
        g_wl[gtid] = __float2bfloat16_rn(v - __bfloat162float(h));
    }

    int warp = gtid >> 5;
    int lane = threadIdx.x & 31;
    if (warp >= NN) return;
    const float* row = H + (size_t)warp * EE;
    int base = 0;
    for (int it = 0; it < EE / 128; it++) {
        float4 v4 = *(const float4*)(row + it * 128 + lane * 4);
        float v[4] = {v4.x, v4.y, v4.z, v4.w};
#pragma unroll
        for (int j = 0; j < 4; j++) {
            unsigned m = __ballot_sync(0xffffffffu, v[j] != 0.0f);
            if (v[j] != 0.0f) {
                int pos = base + __popc(m & ((1u << lane) - 1u));
                if (pos < CAP_R) g_cols[warp * CAP_R + pos] = it * 128 + lane * 4 + j;
            }
            base += __popc(m);
        }
    }
    if (lane == 0) {
        g_rcnt[warp]  = min(base, CAP_R);
        g_invsv[warp] = rsqrtf(fmaxf((float)base, 1.0f));
    }
}

// Fused: CSR->CSC scatter + x0 -> bf16 (pre-scaled by invsv[row]).
__global__ void scatter_cvt_kernel(const float* __restrict__ x0) {
    int tid = blockIdx.x * blockDim.x + threadIdx.x;
    int row = tid >> 7;
    float2 p = *(const float2*)(x0 + (size_t)tid * 2);
    float s = g_invsv[row];
    g_x0bf[tid] = __floats2bfloat162_rn(p.x * s, p.y * s);

    int k = tid & (CAP_R - 1);
    if (k < g_rcnt[row]) {
        int col = g_cols[row * CAP_R + k];
        int p2 = atomicAdd(&g_ccnt[col], 1);
        if (p2 < CAP_C) g_rows[col * CAP_C + p2] = row;
    }
}

// ---------------- SpMM gathers: warp-per-row, LDG.128, bf16-hi output -------
__device__ __forceinline__ void acc8q(float* a, uint4 q) {
    float2 f;
    f = __bfloat1622float2(*(__nv_bfloat162*)&q.x); a[0] += f.x; a[1] += f.y;
    f = __bfloat1622float2(*(__nv_bfloat162*)&q.y); a[2] += f.x; a[3] += f.y;
    f = __bfloat1622float2(*(__nv_bfloat162*)&q.z); a[4] += f.x; a[5] += f.y;
    f = __bfloat1622float2(*(__nv_bfloat162*)&q.w); a[6] += f.x; a[7] += f.y;
}

__device__ __forceinline__ void store_hi8(const float* a, float s,
                                          __nv_bfloat16* out, size_t off) {
    unsigned hq[4];
#pragma unroll
    for (int j = 0; j < 4; j++) {
        __nv_bfloat162 h2 = __floats2bfloat162_rn(a[2*j] * s, a[2*j+1] * s);
        hq[j] = *(unsigned*)&h2;
    }
    *(uint4*)(out + off) = make_uint4(hq[0], hq[1], hq[2], hq[3]);
}

__global__ __launch_bounds__(256) void spmm_edges_kernel(const uint4* __restrict__ src,
                                                         __nv_bfloat16* __restrict__ out) {
    int e    = blockIdx.x * 8 + (threadIdx.x >> 5);
    int lane = threadIdx.x & 31;
    int craw = g_ccnt[e];
    float se = rsqrtf(fmaxf((float)craw, 1.0f));
    if (lane == 0) g_invse[e] = se;
    int cnt = min(craw, CAP_C);
    const int* lst = &g_rows[e * CAP_C];
    float a[8];
#pragma unroll
    for (int r = 0; r < 8; r++) a[r] = 0.0f;
    int k = 0;
    for (; k + 4 <= cnt; k += 4) {
        int4 l = *(const int4*)(lst + k);
        uint4 q0 = src[((unsigned)l.x << 5) + lane];
        uint4 q1 = src[((unsigned)l.y << 5) + lane];
        uint4 q2 = src[((unsigned)l.z << 5) + lane];
        uint4 q3 = src[((unsigned)l.w << 5) + lane];
        acc8q(a, q0); acc8q(a, q1); acc8q(a, q2); acc8q(a, q3);
    }
    for (; k < cnt; k++) {
        acc8q(a, src[((unsigned)lst[k] << 5) + lane]);
    }
    store_hi8(a, se, out, (size_t)e * DIM + lane * 8);
}

__global__ __launch_bounds__(256) void spmm_nodes_kernel(const uint4* __restrict__ src,
                                                         __nv_bfloat16* __restrict__ out) {
    int i    = blockIdx.x * 8 + (threadIdx.x >> 5);
    int lane = threadIdx.x & 31;
    int cnt = g_rcnt[i];
    const int* lst = &g_cols[i * CAP_R];
    float a[8];
#pragma unroll
    for (int r = 0; r < 8; r++) a[r] = 0.0f;
    int k = 0;
    for (; k + 4 <= cnt; k += 4) {
        int4 l = *(const int4*)(lst + k);
        uint4 q0 = src[((unsigned)l.x << 5) + lane];
        uint4 q1 = src[((unsigned)l.y << 5) + lane];
        uint4 q2 = src[((unsigned)l.z << 5) + lane];
        uint4 q3 = src[((unsigned)l.w << 5) + lane];
        acc8q(a, q0); acc8q(a, q1); acc8q(a, q2); acc8q(a, q3);
    }
    for (; k < cnt; k++) {
        acc8q(a, src[((unsigned)lst[k] << 5) + lane]);
    }
    float sv = g_invsv[i];
    store_hi8(a, sv, out, (size_t)i * DIM + lane * 8);
}

// ---------------- tensor-core GEMM: Ah x (Wh+Wl), cp.async 4-stage ----------
__device__ __forceinline__ void mma_bf16(float* c, const unsigned* a, const unsigned* b) {
    asm volatile(
        "mma.sync.aligned.m16n8k16.row.col.f32.bf16.bf16.f32 "
        "{%0,%1,%2,%3}, {%4,%5,%6,%7}, {%8,%9}, {%0,%1,%2,%3};\n"
        : "+f"(c[0]), "+f"(c[1]), "+f"(c[2]), "+f"(c[3])
        : "r"(a[0]), "r"(a[1]), "r"(a[2]), "r"(a[3]), "r"(b[0]), "r"(b[1]));
}
__device__ __forceinline__ void ldsm_x4(unsigned* r, unsigned addr) {
    asm volatile("ldmatrix.sync.aligned.m8n8.x4.shared.b16 {%0,%1,%2,%3}, [%4];"
        : "=r"(r[0]), "=r"(r[1]), "=r"(r[2]), "=r"(r[3]) : "r"(addr));
}
__device__ __forceinline__ void ldsm_x4_t(unsigned& r0, unsigned& r1,
                                          unsigned& r2, unsigned& r3, unsigned addr) {
    asm volatile("ldmatrix.sync.aligned.m8n8.x4.trans.shared.b16 {%0,%1,%2,%3}, [%4];"
        : "=r"(r0), "=r"(r1), "=r"(r2), "=r"(r3) : "r"(addr));
}
#define CP_ASYNC16(dst, src) \
    asm volatile("cp.async.cg.shared.global [%0], [%1], 16;" :: "r"(dst), "l"(src))
#define CP_COMMIT() asm volatile("cp.async.commit_group;")
#define CP_WAIT2()  asm volatile("cp.async.wait_group 2;" ::: "memory")

// CTA tile 64(M) x 128(N), KTILE=16, 4 smem stages (47.1 KB static).
// 8 warps 2(M) x 4(N); warp tile 32x32; 16 MMAs per warp per k-tile.
#define ASTG 3072   // 64*48
#define BSTG 4352   // 16*272

struct GemmSmem {
    unsigned short Ah[4][64][24];
    unsigned short Bh[4][16][136];
    unsigned short Bl[4][16][136];
};

template<bool RESID, bool GELU>
__device__ __forceinline__ void gemm_body(
    GemmSmem* gs, int bx, int by,
    const __nv_bfloat16* __restrict__ Ah_g,
    const __nv_bfloat16* __restrict__ Bh_g, const __nv_bfloat16* __restrict__ Bl_g,
    const float* __restrict__ bias, const float* __restrict__ resid,
    const float* __restrict__ gate, float* __restrict__ C,
    __nv_bfloat162* __restrict__ Ch,
    __nv_bfloat162* __restrict__ bfc, const float* __restrict__ rowscale,
    int N, int K)
{
    const int tid  = threadIdx.x;
    const int warp = tid >> 5;
    const int lane = tid & 31;
    const int l15  = lane & 15;
    const int lhi  = lane >> 4;
    const int grp  = lane >> 2;
    const int qd   = lane & 3;
    const int m0 = by * 64;
    const int n0 = bx * 128;
    const int warpM = (warp >> 2) * 32;
    const int warpN = (warp & 3) * 32;

    const unsigned sAh = (unsigned)__cvta_generic_to_shared(&gs->Ah[0][0][0]);
    const unsigned sBh = (unsigned)__cvta_generic_to_shared(&gs->Bh[0][0][0]);
    const unsigned sBl = (unsigned)__cvta_generic_to_shared(&gs->Bl[0][0][0]);

    float acc[2][4][4];
#pragma unroll
    for (int mf = 0; mf < 2; mf++)
#pragma unroll
        for (int nf = 0; nf < 4; nf++)
#pragma unroll
            for (int r = 0; r < 4; r++) acc[mf][nf][r] = 0.0f;

    const int a_m = tid >> 1;
    const int a_c = tid & 1;
    const int b_k = tid >> 4;
    const int b_c = tid & 15;
    const size_t a_goff = (size_t)(m0 + a_m) * K + a_c * 8;
    const size_t b_goff = (size_t)b_k * N + n0 + b_c * 8;
    const unsigned a_soff = a_m * 48 + a_c * 16;
    const unsigned b_soff = b_k * 272 + b_c * 16;
    const bool a_act = (tid < 128);

    auto issue = [&](int s, int k0) {
        if (a_act) CP_ASYNC16(sAh + s * ASTG + a_soff, Ah_g + a_goff + k0);
        CP_ASYNC16(sBh + s * BSTG + b_soff, Bh_g + b_goff + (size_t)k0 * N);
        CP_ASYNC16(sBl + s * BSTG + b_soff, Bl_g + b_goff + (size_t)k0 * N);
    };

    const int ntiles = K / 16;   // >= 16 for all call sites
    issue(0, 0);  CP_COMMIT();
    issue(1, 16); CP_COMMIT();
    issue(2, 32); CP_COMMIT();

#pragma unroll 1
    for (int t = 0; t < ntiles; t++) {
        CP_WAIT2();
        __syncthreads();
        if (t + 3 < ntiles) issue((t + 3) & 3, (t + 3) * 16);
        CP_COMMIT();

        const int s = t & 3;
        unsigned afh[2][4], bfh[4][2], bfl[4][2];
#pragma unroll
        for (int mf = 0; mf < 2; mf++) {
            unsigned aoff = (unsigned)s * ASTG
                          + (unsigned)(warpM + mf * 16 + l15) * 48u + (unsigned)lhi * 16u;
            ldsm_x4(afh[mf], sAh + aoff);
        }
#pragma unroll
        for (int p = 0; p < 2; p++) {
            unsigned boff = (unsigned)s * BSTG + (unsigned)l15 * 272u
                          + (unsigned)(warpN + p * 16 + lhi * 8) * 2u;
            ldsm_x4_t(bfh[2*p][0], bfh[2*p][1], bfh[2*p+1][0], bfh[2*p+1][1], sBh + boff);
            ldsm_x4_t(bfl[2*p][0], bfl[2*p][1], bfl[2*p+1][0], bfl[2*p+1][1], sBl + boff);
        }
#pragma unroll
        for (int mf = 0; mf < 2; mf++)
#pragma unroll
            for (int nf = 0; nf < 4; nf++) {
                mma_bf16(acc[mf][nf], afh[mf], bfh[nf]);
                mma_bf16(acc[mf][nf], afh[mf], bfl[nf]);
            }
    }

    float alpha = 1.0f;
    if (!GELU && gate != nullptr) alpha = tanhf(gate[0]);

#pragma unroll
    for (int mf = 0; mf < 2; mf++) {
#pragma unroll
        for (int nf = 0; nf < 4; nf++) {
            int col = n0 + warpN + nf * 8 + 2 * qd;
            float bv0 = bias[col], bv1 = bias[col + 1];
            int r0 = m0 + warpM + mf * 16 + grp;
#pragma unroll
            for (int half = 0; half < 2; half++) {
                int row = r0 + half * 8;
                float v0 = acc[mf][nf][half * 2 + 0] + bv0;
                float v1 = acc[mf][nf][half * 2 + 1] + bv1;
                if (GELU) {
                    v0 = 0.5f * v0 * (1.0f + erff(v0 * 0.7071067811865476f));
                    v1 = 0.5f * v1 * (1.0f + erff(v1 * 0.7071067811865476f));
                } else {
                    v0 *= alpha; v1 *= alpha;
                }
                size_t base = (size_t)row * N + col;
                if (RESID) {
                    float2 r = *(const float2*)(resid + base);
                    v0 += r.x; v1 += r.y;
                }
                if (C) *(float2*)(C + base) = make_float2(v0, v1);
                if (Ch) Ch[base >> 1] = __floats2bfloat162_rn(v0, v1);
                if (bfc) {
                    float s = rowscale ? rowscale[row] : 1.0f;
                    bfc[base >> 1] = __floats2bfloat162_rn(v0 * s, v1 * s);
                }
            }
        }
    }
}

// Standalone GEMM kernel (steps 4, 6, 11)
template<bool RESID, bool GELU>
__global__ __launch_bounds__(256, 2) void gemm_tc_kernel(
    const __nv_bfloat16* __restrict__ Ah_g,
    const __nv_bfloat16* __restrict__ Bh_g, const __nv_bfloat16* __restrict__ Bl_g,
    const float* __restrict__ bias, const float* __restrict__ resid,
    const float* __restrict__ gate, float* __restrict__ C,
    __nv_bfloat162* __restrict__ Ch,
    __nv_bfloat162* __restrict__ bfc, const float* __restrict__ rowscale,
    int N, int K)
{
    __shared__ GemmSmem gs;
    gemm_body<RESID, GELU>(&gs, blockIdx.x, blockIdx.y,
                           Ah_g, Bh_g, Bl_g, bias, resid, gate, C, Ch, bfc, rowscale,
                           N, K);
}

// Fused steps 9+10 (both GEMMs, uniform resource class):
//  blocks 0..255    -> x1_out = x1a + tanh(gr)*(ret @ Wr + br)   grid (2,128)
//  blocks 256..1279 -> h = gelu(x0g @ W1 + b1)                   grid (4,256)
__global__ __launch_bounds__(256, 2) void fused_910_kernel(
    const float* __restrict__ br, const float* __restrict__ gr,
    float* __restrict__ out_x1, const float* __restrict__ b1)
{
    __shared__ GemmSmem gs;
    int b = blockIdx.x;
    if (b < 256) {
        gemm_body<true, false>(&gs, b & 1, b >> 1,
                               g_reth, g_wh + OFF_WR, g_wl + OFF_WR, br,
                               g_x1a, gr, out_x1, nullptr, nullptr, nullptr,
                               DIM, DIM);
    } else {
        int id = b - 256;
        gemm_body<false, true>(&gs, id & 3, id >> 2,
                               g_x0gh, g_wh + OFF_W1, g_wl + OFF_W1, b1,
                               nullptr, nullptr, nullptr,
                               (__nv_bfloat162*)g_hh, nullptr, nullptr,
                               2 * DIM, DIM);
    }
}

// ---------------- fused double LayerNorm -------------------------------------
__device__ __forceinline__ float block_sum_256(float v, float* sm) {
#pragma unroll
    for (int o = 16; o > 0; o >>= 1) v += __shfl_xor_sync(0xffffffffu, v, o);
    int w = threadIdx.x >> 5, lane = threadIdx.x & 31;
    if (lane == 0) sm[w] = v;
    __syncthreads();
    if (w == 0) {
        float s = (lane < 8) ? sm[lane] : 0.0f;
#pragma unroll
        for (int o = 4; o > 0; o >>= 1) s += __shfl_xor_sync(0xffffffffu, s, o);
        if (lane == 0) sm[0] = s;
    }
    __syncthreads();
    float r = sm[0];
    __syncthreads();
    return r;
}

__global__ __launch_bounds__(DIM) void ln_double_kernel(
    const float* __restrict__ g1, const float* __restrict__ b1,
    const float* __restrict__ g2, const float* __restrict__ b2)
{
    __shared__ float sm[8];
    int r = blockIdx.x, t = threadIdx.x;
    size_t idx = (size_t)r * DIM + t;
    float v = g_u[idx];
    float mean = block_sum_256(v, sm) * (1.0f / DIM);
    float d = v - mean;
    float var = block_sum_256(d * d, sm) * (1.0f / DIM);
    float y = d * rsqrtf(var + LN_EPS) * g1[t] + b1[t];
    {
        float sv = g_invsv[r];
        float y_hi = __shfl_xor_sync(0xffffffffu, y, 1);
        if ((t & 1) == 0)
            g_x0lbf[idx >> 1] = __floats2bfloat162_rn(y * sv, y_hi * sv);
    }
    float m2 = block_sum_256(y, sm) * (1.0f / DIM);
    float d2 = y - m2;
    float v2 = block_sum_256(d2 * d2, sm) * (1.0f / DIM);
    float z = d2 * rsqrtf(v2 + LN_EPS) * g2[t] + b2[t];
    g_x0g[idx] = z;
    {
        float z_n = __shfl_xor_sync(0xffffffffu, z, 1);
        if ((t & 1) == 0) {
            __nv_bfloat162 h2 = __floats2bfloat162_rn(z, z_n);
            ((unsigned*)g_x0gh)[idx >> 1] = *(unsigned*)&h2;
        }
    }
}

// ---------------- driver -----------------------------------------------------
extern "C" void kernel_launch(void* const* d_in, const int* in_sizes, int n_in,
                              void* d_out, int out_size) {
    const float* x0   = (const float*)d_in[0];
    const float* x1   = (const float*)d_in[1];
    const float* H    = (const float*)d_in[2];
    const float* Wn   = (const float*)d_in[3];
    const float* bn   = (const float*)d_in[4];
    const float* We   = (const float*)d_in[5];
    const float* be   = (const float*)d_in[6];
    const float* Wr   = (const float*)d_in[7];
    const float* br   = (const float*)d_in[8];
    const float* W1   = (const float*)d_in[9];
    const float* b1   = (const float*)d_in[10];
    const float* W2   = (const float*)d_in[11];
    const float* b2   = (const float*)d_in[12];
    const float* ln1g = (const float*)d_in[13];
    const float* ln1b = (const float*)d_in[14];
    const float* ln2g = (const float*)d_in[15];
    const float* ln2b = (const float*)d_in[16];
    const float* gl   = (const float*)d_in[17];
    const float* gr   = (const float*)d_in[18];

    float* out_x0 = (float*)d_out;
    float* out_x1 = (float*)d_out + (size_t)NN * DIM;

    float *p_x1a, *p_u, *p_x0g, *p_invse;
    __nv_bfloat162 *p_x0bf, *p_x1abf, *p_x0lbf;
    __nv_bfloat16 *p_wh, *p_wl;
    __nv_bfloat16 *p_tmpEh, *p_msgh, *p_reth, *p_hh;
    cudaGetSymbolAddress((void**)&p_x1a,  g_x1a);
    cudaGetSymbolAddress((void**)&p_u,    g_u);
    cudaGetSymbolAddress((void**)&p_x0g,  g_x0g);
    cudaGetSymbolAddress((void**)&p_invse, g_invse);
    cudaGetSymbolAddress((void**)&p_x0bf,  g_x0bf);
    cudaGetSymbolAddress((void**)&p_x1abf, g_x1abf);
    cudaGetSymbolAddress((void**)&p_x0lbf, g_x0lbf);
    cudaGetSymbolAddress((void**)&p_wh, g_wh);
    cudaGetSymbolAddress((void**)&p_wl, g_wl);
    cudaGetSymbolAddress((void**)&p_tmpEh, g_tmpEh);
    cudaGetSymbolAddress((void**)&p_msgh, g_msgh);
    cudaGetSymbolAddress((void**)&p_reth, g_reth);
    cudaGetSymbolAddress((void**)&p_hh, g_hh);

    // 1) sparse build + weight prepack (fused, DRAM-bound)
    build_csr_kernel<<<NN / 8, 256>>>(H, We, Wn, Wr, W1, W2);
    // 2) scatter + x0->bf16(*invsv)
    scatter_cvt_kernel<<<(NN * CAP_R) / 256, 256>>>(x0);
    // 3) tmpE = H_norm^T @ x0 -> bf16-hi plane (publishes invse)
    spmm_edges_kernel<<<EE / 8, 256>>>((const uint4*)p_x0bf, p_tmpEh);
    // 4) x1a = x1 + tmpE @ We + be (fp32 + gather copy)   <-- ncu profiled slot
    gemm_tc_kernel<true, false><<<dim3(DIM / 128, EE / 64), 256>>>(
        p_tmpEh, p_wh + OFF_WE, p_wl + OFF_WE, be, x1, nullptr, p_x1a,
        nullptr, p_x1abf, p_invse, DIM, DIM);
    // 5) msg = H_norm @ x1a -> bf16-hi plane
    spmm_nodes_kernel<<<NN / 8, 256>>>((const uint4*)p_x1abf, p_msgh);
    // 6) u = x0 + tanh(gl) * (msg @ Wn + bn)
    gemm_tc_kernel<true, false><<<dim3(DIM / 128, NN / 64), 256>>>(
        p_msgh, p_wh + OFF_WN, p_wl + OFF_WN, bn, x0, gl, p_u,
        nullptr, nullptr, nullptr, DIM, DIM);
    // 7) LN1 (gather copy) + LN2 (fp32 + bf16-hi plane)
    ln_double_kernel<<<NN, DIM>>>(ln1g, ln1b, ln2g, ln2b);
    // 8) ret = H_norm^T @ x0_local -> bf16-hi plane
    spmm_edges_kernel<<<EE / 8, 256>>>((const uint4*)p_x0lbf, p_reth);
    // 9+10) fused: x1_out GEMM || FFN1 GEMM (uniform resource class)
    fused_910_kernel<<<1280, 256>>>(br, gr, out_x1, b1);
    // 11) x0_out = x0_global + h @ W2 + b2   (K = 512)
    gemm_tc_kernel<true, false><<<dim3(DIM / 128, NN / 64), 256>>>(
        p_hh, p_wh + OFF_W2, p_wl + OFF_W2, b2, p_x0g, nullptr, out_x0,
        nullptr, nullptr, nullptr, DIM, 2 * DIM);

    (void)in_sizes; (void)n_in; (void)out_size;
}